// round 13
// baseline (speedup 1.0000x reference)
#include <cuda_runtime.h>
#include <cuda_bf16.h>

// gene_seq (N=256, M=2000) int32 in [0,4); embedding_mat (M=2000, 4, D=128) f32.
// out[n, m, :] = embedding_mat[m, gene_seq[n,m], :] / max(||row||, 1e-12)
//
// Converged shape: MTILE=8, 256-thread blocks, grid (250,4)=1000 blocks,
// register-resident candidate rows per warp, warp-reduced norms, pre-scaled,
// evict-first (.cs) STG.128 stream, 4-way store ILP.
// This round: pack all 64 2-bit gene indices into 4 registers per thread
// (one-time smem read) so the store loop has ZERO memory reads — pure
// shift/and + FSEL + STG.

#define NM 256
#define MM 2000
#define DD 128
#define MTILE 8
#define NTILE 64
#define THREADS 256
#define ROW_F4 (DD / 4)   // 32 float4 per row

__device__ __forceinline__ float4 sel4(int g, const float4& r0, const float4& r1,
                                       const float4& r2, const float4& r3) {
    int hi = g >> 1, lo = g & 1;
    float4 ta, tb, v;
    ta.x = lo ? r1.x : r0.x;  tb.x = lo ? r3.x : r2.x;  v.x = hi ? tb.x : ta.x;
    ta.y = lo ? r1.y : r0.y;  tb.y = lo ? r3.y : r2.y;  v.y = hi ? tb.y : ta.y;
    ta.z = lo ? r1.z : r0.z;  tb.z = lo ? r3.z : r2.z;  v.z = hi ? tb.z : ta.z;
    ta.w = lo ? r1.w : r0.w;  tb.w = lo ? r3.w : r2.w;  v.w = hi ? tb.w : ta.w;
    return v;
}

__global__ void __launch_bounds__(THREADS) embed_kernel(
    const int* __restrict__ seq,
    const float* __restrict__ emb,
    float* __restrict__ out)
{
    __shared__ int sseq[NTILE][MTILE];   // 2 KB

    const int m0   = blockIdx.x * MTILE;
    const int n0   = blockIdx.y * NTILE;
    const int tid  = threadIdx.x;
    const int warp = tid >> 5;
    const int lane = tid & 31;
    const int m    = m0 + warp;

    // --- stage seq tile: seq[n0+j][m0+mm], 64x8 ints ---
    #pragma unroll
    for (int i = 0; i < (NTILE * MTILE) / THREADS; i++) {
        int t  = tid + i * THREADS;
        int j  = t >> 3;
        int mm = t & 7;
        sseq[j][mm] = __ldg(seq + (size_t)(n0 + j) * MM + m0 + mm);
    }

    // --- load this warp's 4 candidate rows into registers, normalize ---
    const float4* src = reinterpret_cast<const float4*>(emb + (size_t)m * 4 * DD);
    float4 r0 = __ldg(src + 0 * ROW_F4 + lane);
    float4 r1 = __ldg(src + 1 * ROW_F4 + lane);
    float4 r2 = __ldg(src + 2 * ROW_F4 + lane);
    float4 r3 = __ldg(src + 3 * ROW_F4 + lane);

    float s0 = r0.x*r0.x + r0.y*r0.y + r0.z*r0.z + r0.w*r0.w;
    float s1 = r1.x*r1.x + r1.y*r1.y + r1.z*r1.z + r1.w*r1.w;
    float s2 = r2.x*r2.x + r2.y*r2.y + r2.z*r2.z + r2.w*r2.w;
    float s3 = r3.x*r3.x + r3.y*r3.y + r3.z*r3.z + r3.w*r3.w;
    #pragma unroll
    for (int off = 16; off > 0; off >>= 1) {
        s0 += __shfl_xor_sync(0xFFFFFFFFu, s0, off);
        s1 += __shfl_xor_sync(0xFFFFFFFFu, s1, off);
        s2 += __shfl_xor_sync(0xFFFFFFFFu, s2, off);
        s3 += __shfl_xor_sync(0xFFFFFFFFu, s3, off);
    }
    float c0 = 1.0f / fmaxf(sqrtf(s0), 1e-12f);
    float c1 = 1.0f / fmaxf(sqrtf(s1), 1e-12f);
    float c2 = 1.0f / fmaxf(sqrtf(s2), 1e-12f);
    float c3 = 1.0f / fmaxf(sqrtf(s3), 1e-12f);
    r0.x *= c0; r0.y *= c0; r0.z *= c0; r0.w *= c0;
    r1.x *= c1; r1.y *= c1; r1.z *= c1; r1.w *= c1;
    r2.x *= c2; r2.y *= c2; r2.z *= c2; r2.w *= c2;
    r3.x *= c3; r3.y *= c3; r3.z *= c3; r3.w *= c3;

    __syncthreads();   // sseq ready

    // --- pack 64 2-bit gene indices into 4 regs (uniform broadcast LDS) ---
    unsigned p0 = 0, p1 = 0, p2 = 0, p3 = 0;
    #pragma unroll
    for (int jj = 0; jj < 16; jj++) {
        p0 |= (unsigned)(sseq[jj     ][warp] & 3) << (2 * jj);
        p1 |= (unsigned)(sseq[jj + 16][warp] & 3) << (2 * jj);
        p2 |= (unsigned)(sseq[jj + 32][warp] & 3) << (2 * jj);
        p3 |= (unsigned)(sseq[jj + 48][warp] & 3) << (2 * jj);
    }

    // --- stream outputs: 64 n's, zero loads in the loop ---
    float4* dst = reinterpret_cast<float4*>(out + ((size_t)n0 * MM + m) * DD) + lane;
    const size_t nstride = (size_t)MM * ROW_F4;   // float4 stride between n's

    #pragma unroll 4
    for (int j = 0; j < 16; j++) {
        int sh = 2 * j;
        int ga = (p0 >> sh) & 3;
        int gb = (p1 >> sh) & 3;
        int gc = (p2 >> sh) & 3;
        int gd = (p3 >> sh) & 3;
        float4 va = sel4(ga, r0, r1, r2, r3);
        float4 vb = sel4(gb, r0, r1, r2, r3);
        float4 vc = sel4(gc, r0, r1, r2, r3);
        float4 vd = sel4(gd, r0, r1, r2, r3);
        __stcs(dst + (size_t)(j     ) * nstride, va);   // STG.E.128 evict-first
        __stcs(dst + (size_t)(j + 16) * nstride, vb);
        __stcs(dst + (size_t)(j + 32) * nstride, vc);
        __stcs(dst + (size_t)(j + 48) * nstride, vd);
    }
}

extern "C" void kernel_launch(void* const* d_in, const int* in_sizes, int n_in,
                              void* d_out, int out_size) {
    const int*   seq = (const int*)d_in[0];     // (256, 2000) int32
    const float* emb = (const float*)d_in[1];   // (2000, 4, 128) f32
    float*       out = (float*)d_out;           // (256, 2000, 128) f32

    dim3 grid(MM / MTILE, NM / NTILE);          // (250, 4)
    embed_kernel<<<grid, THREADS>>>(seq, emb, out);
}

// round 14
// speedup vs baseline: 1.0370x; 1.0370x over previous
#include <cuda_runtime.h>
#include <cuda_bf16.h>

// gene_seq (N=256, M=2000) int32 in [0,4); embedding_mat (M=2000, 4, D=128) f32.
// out[n, m, :] = embedding_mat[m, gene_seq[n,m], :] / max(||row||, 1e-12)
//
// Converged shape (best measured = 43.07us): MTILE=8, 256-thread blocks,
// grid (250,4)=1000 blocks (single wave). Register-resident candidate rows
// per warp, warp-reduced norms, pre-scaled registers, evict-first (.cs)
// STG.128 stream, 4 independent select+store chains per iteration.
// This round: store-loop unroll 4 -> 8 (deeper outstanding-store batching).

#define NM 256
#define MM 2000
#define DD 128
#define MTILE 8
#define NTILE 64
#define THREADS 256
#define ROW_F4 (DD / 4)   // 32 float4 per row

__device__ __forceinline__ float4 sel4(int g, const float4& r0, const float4& r1,
                                       const float4& r2, const float4& r3) {
    int hi = g >> 1, lo = g & 1;
    float4 ta, tb, v;
    ta.x = lo ? r1.x : r0.x;  tb.x = lo ? r3.x : r2.x;  v.x = hi ? tb.x : ta.x;
    ta.y = lo ? r1.y : r0.y;  tb.y = lo ? r3.y : r2.y;  v.y = hi ? tb.y : ta.y;
    ta.z = lo ? r1.z : r0.z;  tb.z = lo ? r3.z : r2.z;  v.z = hi ? tb.z : ta.z;
    ta.w = lo ? r1.w : r0.w;  tb.w = lo ? r3.w : r2.w;  v.w = hi ? tb.w : ta.w;
    return v;
}

__global__ void __launch_bounds__(THREADS) embed_kernel(
    const int* __restrict__ seq,
    const float* __restrict__ emb,
    float* __restrict__ out)
{
    __shared__ int sseq[NTILE][MTILE];   // 2 KB

    const int m0   = blockIdx.x * MTILE;
    const int n0   = blockIdx.y * NTILE;
    const int tid  = threadIdx.x;
    const int warp = tid >> 5;
    const int lane = tid & 31;
    const int m    = m0 + warp;

    // --- stage seq tile: seq[n0+j][m0+mm], 64x8 ints ---
    #pragma unroll
    for (int i = 0; i < (NTILE * MTILE) / THREADS; i++) {
        int t  = tid + i * THREADS;
        int j  = t >> 3;
        int mm = t & 7;
        sseq[j][mm] = __ldg(seq + (size_t)(n0 + j) * MM + m0 + mm);
    }

    // --- load this warp's 4 candidate rows into registers, normalize ---
    const float4* src = reinterpret_cast<const float4*>(emb + (size_t)m * 4 * DD);
    float4 r0 = __ldg(src + 0 * ROW_F4 + lane);
    float4 r1 = __ldg(src + 1 * ROW_F4 + lane);
    float4 r2 = __ldg(src + 2 * ROW_F4 + lane);
    float4 r3 = __ldg(src + 3 * ROW_F4 + lane);

    float s0 = r0.x*r0.x + r0.y*r0.y + r0.z*r0.z + r0.w*r0.w;
    float s1 = r1.x*r1.x + r1.y*r1.y + r1.z*r1.z + r1.w*r1.w;
    float s2 = r2.x*r2.x + r2.y*r2.y + r2.z*r2.z + r2.w*r2.w;
    float s3 = r3.x*r3.x + r3.y*r3.y + r3.z*r3.z + r3.w*r3.w;
    #pragma unroll
    for (int off = 16; off > 0; off >>= 1) {
        s0 += __shfl_xor_sync(0xFFFFFFFFu, s0, off);
        s1 += __shfl_xor_sync(0xFFFFFFFFu, s1, off);
        s2 += __shfl_xor_sync(0xFFFFFFFFu, s2, off);
        s3 += __shfl_xor_sync(0xFFFFFFFFu, s3, off);
    }
    float c0 = 1.0f / fmaxf(sqrtf(s0), 1e-12f);
    float c1 = 1.0f / fmaxf(sqrtf(s1), 1e-12f);
    float c2 = 1.0f / fmaxf(sqrtf(s2), 1e-12f);
    float c3 = 1.0f / fmaxf(sqrtf(s3), 1e-12f);
    r0.x *= c0; r0.y *= c0; r0.z *= c0; r0.w *= c0;
    r1.x *= c1; r1.y *= c1; r1.z *= c1; r1.w *= c1;
    r2.x *= c2; r2.y *= c2; r2.z *= c2; r2.w *= c2;
    r3.x *= c3; r3.y *= c3; r3.z *= c3; r3.w *= c3;

    __syncthreads();   // sseq ready

    // --- stream outputs: 64 n's, 4 independent select+store chains/iter ---
    float4* dst = reinterpret_cast<float4*>(out + ((size_t)n0 * MM + m) * DD) + lane;
    const size_t nstride = (size_t)MM * ROW_F4;   // float4 stride between n's

    #pragma unroll 8
    for (int j = 0; j < NTILE / 4; j++) {
        int ga = sseq[j][warp];
        int gb = sseq[j + 16][warp];
        int gc = sseq[j + 32][warp];
        int gd = sseq[j + 48][warp];
        float4 va = sel4(ga, r0, r1, r2, r3);
        float4 vb = sel4(gb, r0, r1, r2, r3);
        float4 vc = sel4(gc, r0, r1, r2, r3);
        float4 vd = sel4(gd, r0, r1, r2, r3);
        __stcs(dst + (size_t)(j     ) * nstride, va);   // STG.E.128 evict-first
        __stcs(dst + (size_t)(j + 16) * nstride, vb);
        __stcs(dst + (size_t)(j + 32) * nstride, vc);
        __stcs(dst + (size_t)(j + 48) * nstride, vd);
    }
}

extern "C" void kernel_launch(void* const* d_in, const int* in_sizes, int n_in,
                              void* d_out, int out_size) {
    const int*   seq = (const int*)d_in[0];     // (256, 2000) int32
    const float* emb = (const float*)d_in[1];   // (2000, 4, 128) f32
    float*       out = (float*)d_out;           // (256, 2000, 128) f32

    dim3 grid(MM / MTILE, NM / NTILE);          // (250, 4)
    embed_kernel<<<grid, THREADS>>>(seq, emb, out);
}